// round 6
// baseline (speedup 1.0000x reference)
#include <cuda_runtime.h>
#include <cuda_fp16.h>

// S_LSTM: 4-layer elementwise LSTM over a 1024x1024 broadcast grid, T=16.
// One thread per (r,c).
// R6: truly-low register footprint (R5 spilled). ALL per-element weights
//     fp16-packed in smem (1x LDS.128/layer-step); i/f/o column params fp16 +
//     f32 wxc packed in a second uint4 (1x LDS.128); bc f32 in registers.
//     -> ~20 persistent regs, 6 blocks/SM (48 warps), no spills.

#define TT 16
#define HDIM 1024
#define NL 4
#define HH (HDIM * HDIM)

__device__ __forceinline__ float tanh_fast(float x) {
    float r; asm("tanh.approx.f32 %0, %1;" : "=f"(r) : "f"(x)); return r;
}

// sigmoid(z) with u = z/2 supplied: 0.5 + 0.5*tanh(u) ~ fma(u, q(u^2), 0.5)
__device__ __forceinline__ float sigm_poly(float u) {
    const float K2 = 0.049435f;
    const float K1 = -0.162927f;
    const float K0 = 0.499786f;
    float s = u * u;
    float q = fmaf(s, K2, K1);
    q = fmaf(s, q, K0);
    return fmaf(u, q, 0.5f);
}

__device__ __forceinline__ unsigned pack_h2(float a, float b) {
    __half2 h = __floats2half2_rn(a, b);
    return *reinterpret_cast<unsigned*>(&h);
}
__device__ __forceinline__ float2 unpack_h2(unsigned u) {
    __half2 h = *reinterpret_cast<__half2*>(&u);
    return __half22float2(h);
}

__global__ void __launch_bounds__(256, 6) s_lstm_kernel(
    const float* __restrict__ x,
    const float* __restrict__ Wxi, const float* __restrict__ Wxf,
    const float* __restrict__ Wxc, const float* __restrict__ Wxo,
    const float* __restrict__ Whi, const float* __restrict__ Whf,
    const float* __restrict__ Whc, const float* __restrict__ Who,
    const float* __restrict__ Whsi, const float* __restrict__ Whsf,
    const float* __restrict__ Whsc, const float* __restrict__ Whso,
    const float* __restrict__ bi, const float* __restrict__ bf,
    const float* __restrict__ bc, const float* __restrict__ bo,
    float* __restrict__ out)
{
    // Per-element weights, fp16: {h2(whi/2,wsi/2), h2(whf/2,wsf/2),
    //                             h2(who/2,wso/2), h2(whc,wsc)}
    __shared__ uint4 smP[NL][256];
    // Column params: {h2(wxi/2,bi/2), h2(wxf/2,bf/2), h2(wxo/2,bo/2), f32 wxc}
    __shared__ uint4 smC[NL][256];
    // Block-uniform input sequence
    __shared__ float sx[TT];

    const int tid = threadIdx.x;
    const int idx = blockIdx.x * 256 + tid;  // r*H + c
    const int r = idx >> 10;                 // constant within a block
    const int c = idx & (HDIM - 1);

    if (tid < TT) sx[tid] = x[tid * HDIM + r];

    float vbc[NL];  // f32 c-gate biases in registers
#pragma unroll
    for (int l = 0; l < NL; l++) {
        const float wsi_l = (l > 0) ? Whsi[(l - 1) * HH + idx] : 0.0f;
        const float wsf_l = (l > 0) ? Whsf[(l - 1) * HH + idx] : 0.0f;
        const float wso_l = (l > 0) ? Whso[(l - 1) * HH + idx] : 0.0f;
        const float wsc_l = (l > 0) ? Whsc[(l - 1) * HH + idx] : 0.0f;
        smP[l][tid] = make_uint4(
            pack_h2(0.5f * Whi[l * HH + idx], 0.5f * wsi_l),
            pack_h2(0.5f * Whf[l * HH + idx], 0.5f * wsf_l),
            pack_h2(0.5f * Who[l * HH + idx], 0.5f * wso_l),
            pack_h2(Whc[l * HH + idx], wsc_l));
        smC[l][tid] = make_uint4(
            pack_h2(0.5f * Wxi[l * HDIM + c], 0.5f * bi[l * HDIM + c]),
            pack_h2(0.5f * Wxf[l * HDIM + c], 0.5f * bf[l * HDIM + c]),
            pack_h2(0.5f * Wxo[l * HDIM + c], 0.5f * bo[l * HDIM + c]),
            __float_as_uint(Wxc[l * HDIM + c]));
        vbc[l] = bc[l * HDIM + c];
    }
    __syncthreads();  // for sx (param slots are own-thread only)

    float cst[NL], hst[NL];
#pragma unroll
    for (int l = 0; l < NL; l++) { cst[l] = 0.0f; hst[l] = 0.0f; }

    float* outp = out + idx;

#pragma unroll 1
    for (int t = 0; t < TT; t++) {
        const float xt = sx[t];
        float hbelow = 0.0f;
#pragma unroll
        for (int l = 0; l < NL; l++) {
            const uint4 P = smP[l][tid];  // LDS.128
            const uint4 C = smC[l][tid];  // LDS.128

            const float2 wis = unpack_h2(P.x);  // whi/2, wsi/2
            const float2 wfs = unpack_h2(P.y);  // whf/2, wsf/2
            const float2 wos = unpack_h2(P.z);  // who/2, wso/2
            const float2 wcs = unpack_h2(P.w);  // whc,   wsc
            const float2 cib = unpack_h2(C.x);  // wxi/2, bi/2
            const float2 cfb = unpack_h2(C.y);  // wxf/2, bf/2
            const float2 cob = unpack_h2(C.z);  // wxo/2, bo/2
            const float  wxc = __uint_as_float(C.w);

            // half-scaled pre-activations for i/f/o; full for c
            float zi = fmaf(xt, cib.x, fmaf(hst[l], wis.x, fmaf(hbelow, wis.y, cib.y)));
            float zf = fmaf(xt, cfb.x, fmaf(hst[l], wfs.x, fmaf(hbelow, wfs.y, cfb.y)));
            float zo = fmaf(xt, cob.x, fmaf(hst[l], wos.x, fmaf(hbelow, wos.y, cob.y)));
            float zc = fmaf(xt, wxc,   fmaf(hst[l], wcs.x, fmaf(hbelow, wcs.y, vbc[l])));

            float ig = sigm_poly(zi);   // FMA pipe
            float fg = sigm_poly(zf);   // FMA pipe
            float og = sigm_poly(zo);   // FMA pipe
            float cc = tanh_fast(zc);   // MUFU

            float cn = fmaf(fg, cst[l], ig * cc);
            float hn = og * tanh_fast(cn);  // MUFU
            cst[l] = cn;
            hst[l] = hn;

            // ys shape (T, 2, NL, H, H): s=0 -> c, s=1 -> h; streaming stores
            __stcs(&outp[l * HH], cn);
            __stcs(&outp[(NL + l) * HH], hn);

            hbelow = hn;
        }
        outp += 2 * NL * HH;
    }
}

extern "C" void kernel_launch(void* const* d_in, const int* in_sizes, int n_in,
                              void* d_out, int out_size) {
    const float* x    = (const float*)d_in[0];
    const float* Wxi  = (const float*)d_in[1];
    const float* Wxf  = (const float*)d_in[2];
    const float* Wxc  = (const float*)d_in[3];
    const float* Wxo  = (const float*)d_in[4];
    const float* Whi  = (const float*)d_in[5];
    const float* Whf  = (const float*)d_in[6];
    const float* Whc  = (const float*)d_in[7];
    const float* Who  = (const float*)d_in[8];
    const float* Whsi = (const float*)d_in[9];
    const float* Whsf = (const float*)d_in[10];
    const float* Whsc = (const float*)d_in[11];
    const float* Whso = (const float*)d_in[12];
    const float* bi   = (const float*)d_in[13];
    const float* bf   = (const float*)d_in[14];
    const float* bc   = (const float*)d_in[15];
    const float* bo   = (const float*)d_in[16];
    float* out = (float*)d_out;

    dim3 block(256);
    dim3 grid(HH / 256);  // 4096 blocks, one thread per (r,c)
    s_lstm_kernel<<<grid, block>>>(x, Wxi, Wxf, Wxc, Wxo,
                                   Whi, Whf, Whc, Who,
                                   Whsi, Whsf, Whsc, Whso,
                                   bi, bf, bc, bo, out);
}

// round 7
// speedup vs baseline: 2.0599x; 2.0599x over previous
#include <cuda_runtime.h>
#include <cuda_fp16.h>

// S_LSTM: 4-layer elementwise LSTM over a 1024x1024 broadcast grid, T=16.
// One thread per (r,c).
// R7: back to the proven R4 register layout (28 per-element f32 weights in
//     registers, 4 blocks/SM -- R5/R6 showed forced reg caps spill and crush
//     perf). MIO reduction: column params packed into ONE uint4 smem slot
//     {h2(wxi/2,bi/2), h2(wxf/2,bf/2), h2(wxo/2,bo/2), f32 wxc}; bc in f32
//     registers. In-loop MIO per layer-step: 2 LDS + 2 STG -> 1 LDS + 2 STG.

#define TT 16
#define HDIM 1024
#define NL 4
#define HH (HDIM * HDIM)

__device__ __forceinline__ float tanh_fast(float x) {
    float r; asm("tanh.approx.f32 %0, %1;" : "=f"(r) : "f"(x)); return r;
}

// sigmoid(z) with u = z/2 supplied: 0.5 + 0.5*tanh(u) ~ fma(u, q(u^2), 0.5)
__device__ __forceinline__ float sigm_poly(float u) {
    const float K2 = 0.049435f;
    const float K1 = -0.162927f;
    const float K0 = 0.499786f;
    float s = u * u;
    float q = fmaf(s, K2, K1);
    q = fmaf(s, q, K0);
    return fmaf(u, q, 0.5f);
}

__device__ __forceinline__ unsigned pack_h2(float a, float b) {
    __half2 h = __floats2half2_rn(a, b);
    return *reinterpret_cast<unsigned*>(&h);
}
__device__ __forceinline__ float2 unpack_h2(unsigned u) {
    __half2 h = *reinterpret_cast<__half2*>(&u);
    return __half22float2(h);
}

__global__ void __launch_bounds__(256, 4) s_lstm_kernel(
    const float* __restrict__ x,
    const float* __restrict__ Wxi, const float* __restrict__ Wxf,
    const float* __restrict__ Wxc, const float* __restrict__ Wxo,
    const float* __restrict__ Whi, const float* __restrict__ Whf,
    const float* __restrict__ Whc, const float* __restrict__ Who,
    const float* __restrict__ Whsi, const float* __restrict__ Whsf,
    const float* __restrict__ Whsc, const float* __restrict__ Whso,
    const float* __restrict__ bi, const float* __restrict__ bf,
    const float* __restrict__ bc, const float* __restrict__ bo,
    float* __restrict__ out)
{
    // One 16B col-param slot per (layer, tid):
    // {h2(wxi/2,bi/2), h2(wxf/2,bf/2), h2(wxo/2,bo/2), f32 wxc}
    __shared__ uint4 smC[NL][256];
    __shared__ float sx[TT];

    const int tid = threadIdx.x;
    const int idx = blockIdx.x * 256 + tid;  // r*H + c
    const int r = idx >> 10;                 // constant within a block
    const int c = idx & (HDIM - 1);

    if (tid < TT) sx[tid] = x[tid * HDIM + r];

    float vbc[NL];
#pragma unroll
    for (int l = 0; l < NL; l++) {
        smC[l][tid] = make_uint4(
            pack_h2(0.5f * Wxi[l * HDIM + c], 0.5f * bi[l * HDIM + c]),
            pack_h2(0.5f * Wxf[l * HDIM + c], 0.5f * bf[l * HDIM + c]),
            pack_h2(0.5f * Wxo[l * HDIM + c], 0.5f * bo[l * HDIM + c]),
            __float_as_uint(Wxc[l * HDIM + c]));
        vbc[l] = bc[l * HDIM + c];
    }
    __syncthreads();  // for sx (param slots are own-thread only)

    // Per-element recurrent weights in f32 registers (i/f/o pre-scaled 0.5).
    float whi[NL], whf[NL], whc[NL], who[NL];
    float wsi[NL - 1], wsf[NL - 1], wsc[NL - 1], wso[NL - 1];

#pragma unroll
    for (int l = 0; l < NL; l++) {
        whi[l] = 0.5f * Whi[l * HH + idx];
        whf[l] = 0.5f * Whf[l * HH + idx];
        who[l] = 0.5f * Who[l * HH + idx];
        whc[l] = Whc[l * HH + idx];
    }
#pragma unroll
    for (int l = 0; l < NL - 1; l++) {
        wsi[l] = 0.5f * Whsi[l * HH + idx];
        wsf[l] = 0.5f * Whsf[l * HH + idx];
        wso[l] = 0.5f * Whso[l * HH + idx];
        wsc[l] = Whsc[l * HH + idx];
    }

    float cst[NL], hst[NL];
#pragma unroll
    for (int l = 0; l < NL; l++) { cst[l] = 0.0f; hst[l] = 0.0f; }

    float* outp = out + idx;

#pragma unroll 1
    for (int t = 0; t < TT; t++) {
        const float xt = sx[t];
        float hbelow = 0.0f;
#pragma unroll
        for (int l = 0; l < NL; l++) {
            const uint4 C = smC[l][tid];        // LDS.128 (only in-loop LDS)
            const float2 cib = unpack_h2(C.x);  // wxi/2, bi/2
            const float2 cfb = unpack_h2(C.y);  // wxf/2, bf/2
            const float2 cob = unpack_h2(C.z);  // wxo/2, bo/2
            const float  wxc = __uint_as_float(C.w);

            const float si = (l > 0) ? hbelow * wsi[l - 1] : 0.0f;
            const float sf = (l > 0) ? hbelow * wsf[l - 1] : 0.0f;
            const float so = (l > 0) ? hbelow * wso[l - 1] : 0.0f;
            const float sc = (l > 0) ? hbelow * wsc[l - 1] : 0.0f;

            // half-scaled pre-activations for i/f/o; full for c
            float zi = fmaf(xt, cib.x, fmaf(hst[l], whi[l], si + cib.y));
            float zf = fmaf(xt, cfb.x, fmaf(hst[l], whf[l], sf + cfb.y));
            float zo = fmaf(xt, cob.x, fmaf(hst[l], who[l], so + cob.y));
            float zc = fmaf(xt, wxc,   fmaf(hst[l], whc[l], sc + vbc[l]));

            float ig = sigm_poly(zi);   // FMA pipe
            float fg = sigm_poly(zf);   // FMA pipe
            float og = sigm_poly(zo);   // FMA pipe
            float cc = tanh_fast(zc);   // MUFU

            float cn = fmaf(fg, cst[l], ig * cc);
            float hn = og * tanh_fast(cn);  // MUFU
            cst[l] = cn;
            hst[l] = hn;

            // ys shape (T, 2, NL, H, H): s=0 -> c, s=1 -> h; streaming stores
            __stcs(&outp[l * HH], cn);
            __stcs(&outp[(NL + l) * HH], hn);

            hbelow = hn;
        }
        outp += 2 * NL * HH;
    }
}

extern "C" void kernel_launch(void* const* d_in, const int* in_sizes, int n_in,
                              void* d_out, int out_size) {
    const float* x    = (const float*)d_in[0];
    const float* Wxi  = (const float*)d_in[1];
    const float* Wxf  = (const float*)d_in[2];
    const float* Wxc  = (const float*)d_in[3];
    const float* Wxo  = (const float*)d_in[4];
    const float* Whi  = (const float*)d_in[5];
    const float* Whf  = (const float*)d_in[6];
    const float* Whc  = (const float*)d_in[7];
    const float* Who  = (const float*)d_in[8];
    const float* Whsi = (const float*)d_in[9];
    const float* Whsf = (const float*)d_in[10];
    const float* Whsc = (const float*)d_in[11];
    const float* Whso = (const float*)d_in[12];
    const float* bi   = (const float*)d_in[13];
    const float* bf   = (const float*)d_in[14];
    const float* bc   = (const float*)d_in[15];
    const float* bo   = (const float*)d_in[16];
    float* out = (float*)d_out;

    dim3 block(256);
    dim3 grid(HH / 256);  // 4096 blocks, one thread per (r,c)
    s_lstm_kernel<<<grid, block>>>(x, Wxi, Wxf, Wxc, Wxo,
                                   Whi, Whf, Whc, Who,
                                   Whsi, Whsf, Whsc, Whso,
                                   bi, bf, bc, bo, out);
}

// round 8
// speedup vs baseline: 2.2167x; 1.0761x over previous
#include <cuda_runtime.h>
#include <cstdint>

// S_LSTM: 4-layer elementwise LSTM over a 1024x1024 broadcast grid, T=16.
// One thread per (r,c). R8 = R4 champion layout + packed f32x2 math:
//   - (zi,zf) and (zo,zc) pre-activations via fma.rn.f32x2 (FFMA2): 12 FFMA -> 6 FFMA2
//   - sigmoid poly evaluated pairwise on (i,f): 8 FFMA -> 4 FFMA2
//   - o-gate sigmoid via MUFU.TANH identity (frees packed consts)
//   - skip weights in smem (frees 12 persistent regs for pair alignment)
// Smem operands stored pre-paired (ulonglong2) so LDS.128 delivers f32x2
// operands directly into register pairs.

#define TT 16
#define HDIM 1024
#define NL 4
#define HH (HDIM * HDIM)

#define FMA2(d, a, b, c) asm("fma.rn.f32x2 %0, %1, %2, %3;" : "=l"(d) : "l"(a), "l"(b), "l"(c))
#define MUL2(d, a, b)    asm("mul.rn.f32x2 %0, %1, %2;"     : "=l"(d) : "l"(a), "l"(b))

__device__ __forceinline__ float tanh_fast(float x) {
    float r; asm("tanh.approx.f32 %0, %1;" : "=f"(r) : "f"(x)); return r;
}
__device__ __forceinline__ uint64_t pk2(float lo, float hi) {
    uint64_t r; unsigned a = __float_as_uint(lo), b = __float_as_uint(hi);
    asm("mov.b64 %0, {%1, %2};" : "=l"(r) : "r"(a), "r"(b)); return r;
}
__device__ __forceinline__ float2 up2(uint64_t v) {
    unsigned a, b; asm("mov.b64 {%0, %1}, %2;" : "=r"(a), "=r"(b) : "l"(v));
    return make_float2(__uint_as_float(a), __uint_as_float(b));
}

__global__ void __launch_bounds__(256, 4) s_lstm_kernel(
    const float* __restrict__ x,
    const float* __restrict__ Wxi, const float* __restrict__ Wxf,
    const float* __restrict__ Wxc, const float* __restrict__ Wxo,
    const float* __restrict__ Whi, const float* __restrict__ Whf,
    const float* __restrict__ Whc, const float* __restrict__ Who,
    const float* __restrict__ Whsi, const float* __restrict__ Whsf,
    const float* __restrict__ Whsc, const float* __restrict__ Whso,
    const float* __restrict__ bi, const float* __restrict__ bf,
    const float* __restrict__ bc, const float* __restrict__ bo,
    float* __restrict__ out)
{
    // A: x = pack(wxi/2, wxf/2), y = pack(bi/2, bf/2)
    // B: x = pack(wxo/2, wxc),   y = pack(bo/2, bc)
    // S: x = pack(wsi/2, wsf/2), y = pack(wso/2, wsc)   (layers 1..3)
    __shared__ ulonglong2 smA[NL][256];
    __shared__ ulonglong2 smB[NL][256];
    __shared__ ulonglong2 smS[NL - 1][256];
    __shared__ float sx[TT];

    const int tid = threadIdx.x;
    const int idx = blockIdx.x * 256 + tid;  // r*H + c
    const int r = idx >> 10;                 // constant within a block
    const int c = idx & (HDIM - 1);

    if (tid < TT) sx[tid] = x[tid * HDIM + r];

#pragma unroll
    for (int l = 0; l < NL; l++) {
        smA[l][tid] = make_ulonglong2(
            pk2(0.5f * Wxi[l * HDIM + c], 0.5f * Wxf[l * HDIM + c]),
            pk2(0.5f * bi[l * HDIM + c],  0.5f * bf[l * HDIM + c]));
        smB[l][tid] = make_ulonglong2(
            pk2(0.5f * Wxo[l * HDIM + c], Wxc[l * HDIM + c]),
            pk2(0.5f * bo[l * HDIM + c],  bc[l * HDIM + c]));
    }
#pragma unroll
    for (int l = 0; l < NL - 1; l++) {
        smS[l][tid] = make_ulonglong2(
            pk2(0.5f * Whsi[l * HH + idx], 0.5f * Whsf[l * HH + idx]),
            pk2(0.5f * Whso[l * HH + idx], Whsc[l * HH + idx]));
    }
    __syncthreads();  // for sx (param slots are own-thread only)

    // Per-element recurrent weights, pre-paired in registers.
    uint64_t whif[NL], whoc[NL];
#pragma unroll
    for (int l = 0; l < NL; l++) {
        whif[l] = pk2(0.5f * Whi[l * HH + idx], 0.5f * Whf[l * HH + idx]);
        whoc[l] = pk2(0.5f * Who[l * HH + idx], Whc[l * HH + idx]);
    }

    // Packed poly constants for the (i,f) sigmoid pair.
    const uint64_t K2_2 = pk2(0.049435f, 0.049435f);
    const uint64_t K1_2 = pk2(-0.162927f, -0.162927f);
    const uint64_t K0_2 = pk2(0.499786f, 0.499786f);
    const uint64_t H5_2 = pk2(0.5f, 0.5f);

    float cst[NL], hst[NL];
#pragma unroll
    for (int l = 0; l < NL; l++) { cst[l] = 0.0f; hst[l] = 0.0f; }

    float* outp = out + idx;

#pragma unroll 1
    for (int t = 0; t < TT; t++) {
        const float xt = sx[t];
        const uint64_t xt2 = pk2(xt, xt);
        float hbelow = 0.0f;
#pragma unroll
        for (int l = 0; l < NL; l++) {
            const ulonglong2 A = smA[l][tid];  // LDS.128
            const ulonglong2 B = smB[l][tid];  // LDS.128
            const uint64_t h2 = pk2(hst[l], hst[l]);

            uint64_t zif, zoc;
            FMA2(zif, h2, whif[l], A.y);
            FMA2(zoc, h2, whoc[l], B.y);
            if (l > 0) {
                const ulonglong2 S = smS[l - 1][tid];  // LDS.128
                const uint64_t hb2 = pk2(hbelow, hbelow);
                FMA2(zif, hb2, S.x, zif);
                FMA2(zoc, hb2, S.y, zoc);
            }
            FMA2(zif, xt2, A.x, zif);
            FMA2(zoc, xt2, B.x, zoc);

            // paired sigmoid poly for (i,f): sig = fma(u, q(u*u), 0.5)
            uint64_t s2, q2, sig2;
            MUL2(s2, zif, zif);
            FMA2(q2, s2, K2_2, K1_2);
            FMA2(q2, s2, q2, K0_2);
            FMA2(sig2, zif, q2, H5_2);
            const float2 igfg = up2(sig2);

            const float2 zocv = up2(zoc);            // (zo/2, zc)
            const float og = fmaf(tanh_fast(zocv.x), 0.5f, 0.5f);  // MUFU
            const float cc = tanh_fast(zocv.y);                     // MUFU

            const float cn = fmaf(igfg.y, cst[l], igfg.x * cc);
            const float hn = og * tanh_fast(cn);                    // MUFU
            cst[l] = cn;
            hst[l] = hn;

            // ys shape (T, 2, NL, H, H): s=0 -> c, s=1 -> h; streaming stores
            __stcs(&outp[l * HH], cn);
            __stcs(&outp[(NL + l) * HH], hn);

            hbelow = hn;
        }
        outp += 2 * NL * HH;
    }
}

extern "C" void kernel_launch(void* const* d_in, const int* in_sizes, int n_in,
                              void* d_out, int out_size) {
    const float* x    = (const float*)d_in[0];
    const float* Wxi  = (const float*)d_in[1];
    const float* Wxf  = (const float*)d_in[2];
    const float* Wxc  = (const float*)d_in[3];
    const float* Wxo  = (const float*)d_in[4];
    const float* Whi  = (const float*)d_in[5];
    const float* Whf  = (const float*)d_in[6];
    const float* Whc  = (const float*)d_in[7];
    const float* Who  = (const float*)d_in[8];
    const float* Whsi = (const float*)d_in[9];
    const float* Whsf = (const float*)d_in[10];
    const float* Whsc = (const float*)d_in[11];
    const float* Whso = (const float*)d_in[12];
    const float* bi   = (const float*)d_in[13];
    const float* bf   = (const float*)d_in[14];
    const float* bc   = (const float*)d_in[15];
    const float* bo   = (const float*)d_in[16];
    float* out = (float*)d_out;

    dim3 block(256);
    dim3 grid(HH / 256);  // 4096 blocks, one thread per (r,c)
    s_lstm_kernel<<<grid, block>>>(x, Wxi, Wxf, Wxc, Wxo,
                                   Whi, Whf, Whc, Who,
                                   Whsi, Whsf, Whsc, Whso,
                                   bi, bf, bc, bo, out);
}

// round 9
// speedup vs baseline: 2.5648x; 1.1570x over previous
#include <cuda_runtime.h>
#include <cstdint>

// S_LSTM: 4-layer elementwise LSTM over a 1024x1024 broadcast grid, T=16.
// One thread per (r,c).
// R9: LOOP SWAP (l outer, t inner). Cross-layer coupling carried in a
//     16-register hb[] array. All per-layer params loaded ONCE per layer into
//     registers (t-invariant) -> inner loop has only 2 STG + 1 broadcast LDS.
//     L1 wavefronts per layer-step: ~13 -> ~3 (L1 was the measured binding
//     resource at 92.2%). f32x2 packed math kept from R8.

#define TT 16
#define HDIM 1024
#define NL 4
#define HH (HDIM * HDIM)

#define FMA2(d, a, b, c) asm("fma.rn.f32x2 %0, %1, %2, %3;" : "=l"(d) : "l"(a), "l"(b), "l"(c))
#define MUL2(d, a, b)    asm("mul.rn.f32x2 %0, %1, %2;"     : "=l"(d) : "l"(a), "l"(b))

__device__ __forceinline__ float tanh_fast(float x) {
    float r; asm("tanh.approx.f32 %0, %1;" : "=f"(r) : "f"(x)); return r;
}
__device__ __forceinline__ uint64_t pk2(float lo, float hi) {
    uint64_t r; unsigned a = __float_as_uint(lo), b = __float_as_uint(hi);
    asm("mov.b64 %0, {%1, %2};" : "=l"(r) : "r"(a), "r"(b)); return r;
}
__device__ __forceinline__ float2 up2(uint64_t v) {
    unsigned a, b; asm("mov.b64 {%0, %1}, %2;" : "=r"(a), "=r"(b) : "l"(v));
    return make_float2(__uint_as_float(a), __uint_as_float(b));
}

__global__ void __launch_bounds__(256, 4) s_lstm_kernel(
    const float* __restrict__ x,
    const float* __restrict__ Wxi, const float* __restrict__ Wxf,
    const float* __restrict__ Wxc, const float* __restrict__ Wxo,
    const float* __restrict__ Whi, const float* __restrict__ Whf,
    const float* __restrict__ Whc, const float* __restrict__ Who,
    const float* __restrict__ Whsi, const float* __restrict__ Whsf,
    const float* __restrict__ Whsc, const float* __restrict__ Whso,
    const float* __restrict__ bi, const float* __restrict__ bf,
    const float* __restrict__ bc, const float* __restrict__ bo,
    float* __restrict__ out)
{
    __shared__ float sx[TT];

    const int tid = threadIdx.x;
    const int idx = blockIdx.x * 256 + tid;  // r*H + c
    const int r = idx >> 10;                 // constant within a block
    const int c = idx & (HDIM - 1);

    if (tid < TT) sx[tid] = x[tid * HDIM + r];
    __syncthreads();

    // Packed poly constants for the (i,f) sigmoid pair.
    const uint64_t K2_2 = pk2(0.049435f, 0.049435f);
    const uint64_t K1_2 = pk2(-0.162927f, -0.162927f);
    const uint64_t K0_2 = pk2(0.499786f, 0.499786f);
    const uint64_t H5_2 = pk2(0.5f, 0.5f);

    // h of the layer below, per timestep (register array, fully unrolled use)
    float hb[TT];
#pragma unroll
    for (int t = 0; t < TT; t++) hb[t] = 0.0f;

#pragma unroll 1
    for (int l = 0; l < NL; l++) {
        // ---- per-layer params, loaded once (t-invariant) ----
        const uint64_t Ax = pk2(0.5f * Wxi[l * HDIM + c], 0.5f * Wxf[l * HDIM + c]);
        const uint64_t Ay = pk2(0.5f * bi[l * HDIM + c],  0.5f * bf[l * HDIM + c]);
        const uint64_t Bx = pk2(0.5f * Wxo[l * HDIM + c], Wxc[l * HDIM + c]);
        const uint64_t By = pk2(0.5f * bo[l * HDIM + c],  bc[l * HDIM + c]);
        const uint64_t whif = pk2(0.5f * Whi[l * HH + idx], 0.5f * Whf[l * HH + idx]);
        const uint64_t whoc = pk2(0.5f * Who[l * HH + idx], Whc[l * HH + idx]);
        uint64_t wsif, wsoc;
        if (l > 0) {
            wsif = pk2(0.5f * Whsi[(l - 1) * HH + idx], 0.5f * Whsf[(l - 1) * HH + idx]);
            wsoc = pk2(0.5f * Whso[(l - 1) * HH + idx], Whsc[(l - 1) * HH + idx]);
        } else {
            wsif = pk2(0.0f, 0.0f);
            wsoc = pk2(0.0f, 0.0f);
        }

        float cl = 0.0f, hl = 0.0f;
        float* pc = out + idx + l * HH;       // c plane of this layer, t=0
        float* ph = pc + NL * HH;             // h plane

#pragma unroll
        for (int t = 0; t < TT; t++) {
            const float xt = sx[t];           // broadcast LDS
            const uint64_t xt2 = pk2(xt, xt);
            const uint64_t h2  = pk2(hl, hl);
            const uint64_t hb2 = pk2(hb[t], hb[t]);

            uint64_t zif, zoc;
            FMA2(zif, h2, whif, Ay);
            FMA2(zif, hb2, wsif, zif);
            FMA2(zif, xt2, Ax, zif);
            FMA2(zoc, h2, whoc, By);
            FMA2(zoc, hb2, wsoc, zoc);
            FMA2(zoc, xt2, Bx, zoc);

            // paired sigmoid poly for (i,f): sig = fma(u, q(u*u), 0.5)
            uint64_t s2, q2, sig2;
            MUL2(s2, zif, zif);
            FMA2(q2, s2, K2_2, K1_2);
            FMA2(q2, s2, q2, K0_2);
            FMA2(sig2, zif, q2, H5_2);
            const float2 igfg = up2(sig2);

            const float2 zocv = up2(zoc);                            // (zo/2, zc)
            const float og = fmaf(tanh_fast(zocv.x), 0.5f, 0.5f);    // MUFU
            const float cc = tanh_fast(zocv.y);                      // MUFU

            const float cn = fmaf(igfg.y, cl, igfg.x * cc);
            const float hn = og * tanh_fast(cn);                     // MUFU
            cl = cn;
            hl = hn;
            hb[t] = hn;  // expose to the layer above

            __stcs(pc, cn);
            __stcs(ph, hn);
            pc += 2 * NL * HH;
            ph += 2 * NL * HH;
        }
    }
}

extern "C" void kernel_launch(void* const* d_in, const int* in_sizes, int n_in,
                              void* d_out, int out_size) {
    const float* x    = (const float*)d_in[0];
    const float* Wxi  = (const float*)d_in[1];
    const float* Wxf  = (const float*)d_in[2];
    const float* Wxc  = (const float*)d_in[3];
    const float* Wxo  = (const float*)d_in[4];
    const float* Whi  = (const float*)d_in[5];
    const float* Whf  = (const float*)d_in[6];
    const float* Whc  = (const float*)d_in[7];
    const float* Who  = (const float*)d_in[8];
    const float* Whsi = (const float*)d_in[9];
    const float* Whsf = (const float*)d_in[10];
    const float* Whsc = (const float*)d_in[11];
    const float* Whso = (const float*)d_in[12];
    const float* bi   = (const float*)d_in[13];
    const float* bf   = (const float*)d_in[14];
    const float* bc   = (const float*)d_in[15];
    const float* bo   = (const float*)d_in[16];
    float* out = (float*)d_out;

    dim3 block(256);
    dim3 grid(HH / 256);  // 4096 blocks, one thread per (r,c)
    s_lstm_kernel<<<grid, block>>>(x, Wxi, Wxf, Wxc, Wxo,
                                   Whi, Whf, Whc, Who,
                                   Whsi, Whsf, Whsc, Whso,
                                   bi, bf, bc, bo, out);
}